// round 1
// baseline (speedup 1.0000x reference)
#include <cuda_runtime.h>
#include <math_constants.h>

#define BATCH 16
#define CDIM  512
#define NPOS  4096      // 64*64
#define O3    1536      // 3*HID
#define HID   512
#define HEADS 8
#define DH    64
#define EPSV  1e-5f
#define QSCALE 0.125f   // DH^-0.5

// ---------------- scratch (device globals; no allocations allowed) ---------
__device__ float g_xn  [(size_t)BATCH * CDIM * NPOS];   // 134 MB
__device__ float g_qkv [(size_t)BATCH * O3   * NPOS];   // 402 MB
__device__ float g_attn[(size_t)BATCH * CDIM * NPOS];   // 134 MB
__device__ float g_ctx [(size_t)BATCH * HEADS * DH * DH]; // 2 MB

// ---------------- channel layernorm (mean/var over C, per (b,p)) ----------
__global__ __launch_bounds__(256) void chan_ln_kernel(
    const float* __restrict__ in, const float* __restrict__ g,
    float* __restrict__ out)
{
    int gid = blockIdx.x * 256 + threadIdx.x;       // over BATCH*NPOS columns
    int b = gid >> 12;                              // NPOS = 4096 = 2^12
    int p = gid & (NPOS - 1);
    const float* ip = in  + (size_t)b * CDIM * NPOS + p;
    float*       op = out + (size_t)b * CDIM * NPOS + p;

    float s = 0.f, s2 = 0.f;
    #pragma unroll 8
    for (int c = 0; c < CDIM; c++) {
        float v = ip[(size_t)c * NPOS];
        s += v; s2 += v * v;
    }
    float mean = s * (1.f / CDIM);
    float var  = s2 * (1.f / CDIM) - mean * mean;
    float rstd = rsqrtf(var + EPSV);

    #pragma unroll 8
    for (int c = 0; c < CDIM; c++) {
        float v = ip[(size_t)c * NPOS];
        op[(size_t)c * NPOS] = (v - mean) * rstd * g[c];
    }
}

// ---------------- fp32 SGEMM: C[z] = A(MxK) * B[z](KxN) (+bias) -----------
// A row-major weights (shared across batch), B batch-strided row-major.
#define BM 128
#define BN 128
#define BK 16
__global__ __launch_bounds__(256) void sgemm_kernel(
    const float* __restrict__ A, const float* __restrict__ B,
    float* __restrict__ C, int M, int N, int K,
    const float* __restrict__ bias)
{
    __shared__ float As[BK][BM];   // stored transposed
    __shared__ float Bs[BK][BN];

    int z = blockIdx.z;
    const float* Bp = B + (size_t)z * K * N;
    float*       Cp = C + (size_t)z * M * N;
    int bm = blockIdx.y * BM;
    int bn = blockIdx.x * BN;
    int tid = threadIdx.x;
    int ty = tid >> 4;             // 0..15
    int tx = tid & 15;             // 0..15

    float acc[8][8];
    #pragma unroll
    for (int i = 0; i < 8; i++)
        #pragma unroll
        for (int j = 0; j < 8; j++) acc[i][j] = 0.f;

    for (int k0 = 0; k0 < K; k0 += BK) {
        // A tile: BM x BK = 2048 floats = 512 float4; 2 per thread
        #pragma unroll
        for (int l = 0; l < 2; l++) {
            int f = tid + l * 256;
            int row = f >> 2;                 // BK/4 = 4 float4 per row
            int c4  = (f & 3) << 2;
            float4 v = *(const float4*)&A[(size_t)(bm + row) * K + k0 + c4];
            As[c4 + 0][row] = v.x; As[c4 + 1][row] = v.y;
            As[c4 + 2][row] = v.z; As[c4 + 3][row] = v.w;
        }
        // B tile: BK x BN = 2048 floats = 512 float4; 2 per thread
        #pragma unroll
        for (int l = 0; l < 2; l++) {
            int f = tid + l * 256;
            int row = f >> 5;                 // BN/4 = 32 float4 per row
            int c4  = (f & 31) << 2;
            *(float4*)&Bs[row][c4] =
                *(const float4*)&Bp[(size_t)(k0 + row) * N + bn + c4];
        }
        __syncthreads();

        #pragma unroll
        for (int kk = 0; kk < BK; kk++) {
            float4 a0 = *(const float4*)&As[kk][ty * 8];
            float4 a1 = *(const float4*)&As[kk][ty * 8 + 4];
            float4 b0 = *(const float4*)&Bs[kk][tx * 8];
            float4 b1 = *(const float4*)&Bs[kk][tx * 8 + 4];
            float ra[8] = {a0.x, a0.y, a0.z, a0.w, a1.x, a1.y, a1.z, a1.w};
            float rb[8] = {b0.x, b0.y, b0.z, b0.w, b1.x, b1.y, b1.z, b1.w};
            #pragma unroll
            for (int i = 0; i < 8; i++)
                #pragma unroll
                for (int j = 0; j < 8; j++)
                    acc[i][j] += ra[i] * rb[j];
        }
        __syncthreads();
    }

    #pragma unroll
    for (int i = 0; i < 8; i++) {
        int orow = bm + ty * 8 + i;
        float bb = bias ? bias[orow] : 0.f;
        #pragma unroll
        for (int j = 0; j < 8; j += 4) {
            float4 v;
            v.x = acc[i][j + 0] + bb; v.y = acc[i][j + 1] + bb;
            v.z = acc[i][j + 2] + bb; v.w = acc[i][j + 3] + bb;
            *(float4*)&Cp[(size_t)orow * N + bn + tx * 8 + j] = v;
        }
    }
}

// ---------------- softmax over head-dim (axis=-2) for q, then *scale ------
__global__ __launch_bounds__(256) void softmax_q_kernel(float* __restrict__ qkv)
{
    int gid = blockIdx.x * 256 + threadIdx.x;     // over BATCH*HEADS*NPOS
    int p  = gid & (NPOS - 1);
    int bm = gid >> 12;
    int m = bm & (HEADS - 1);
    int b = bm >> 3;
    float* base = qkv + (size_t)b * O3 * NPOS + (size_t)(m * DH) * NPOS + p;

    float v[DH];
    float mx = -CUDART_INF_F;
    #pragma unroll
    for (int i = 0; i < DH; i++) {
        v[i] = base[(size_t)i * NPOS];
        mx = fmaxf(mx, v[i]);
    }
    float s = 0.f;
    #pragma unroll
    for (int i = 0; i < DH; i++) {
        v[i] = __expf(v[i] - mx);
        s += v[i];
    }
    float r = QSCALE / s;
    #pragma unroll
    for (int i = 0; i < DH; i++)
        base[(size_t)i * NPOS] = v[i] * r;
}

// ---------------- softmax over n (axis=-1) for k ---------------------------
__device__ __forceinline__ float warp_max(float v) {
    #pragma unroll
    for (int o = 16; o > 0; o >>= 1) v = fmaxf(v, __shfl_xor_sync(0xffffffffu, v, o));
    return v;
}
__device__ __forceinline__ float warp_sum(float v) {
    #pragma unroll
    for (int o = 16; o > 0; o >>= 1) v += __shfl_xor_sync(0xffffffffu, v, o);
    return v;
}

__global__ __launch_bounds__(256) void softmax_k_kernel(float* __restrict__ qkv)
{
    __shared__ float red[8];
    int row = blockIdx.x;                  // BATCH*HEADS*DH rows
    int i = row & (DH - 1);
    int m = (row >> 6) & (HEADS - 1);
    int b = row >> 9;
    float* base = qkv + (size_t)b * O3 * NPOS
                      + (size_t)(HID + m * DH + i) * NPOS;
    int t = threadIdx.x;
    int lane = t & 31, wid = t >> 5;

    float v[16];
    float mx = -CUDART_INF_F;
    #pragma unroll
    for (int u = 0; u < 16; u++) {
        v[u] = base[u * 256 + t];
        mx = fmaxf(mx, v[u]);
    }
    mx = warp_max(mx);
    if (lane == 0) red[wid] = mx;
    __syncthreads();
    mx = warp_max((lane < 8) ? red[lane] : -CUDART_INF_F);
    mx = __shfl_sync(0xffffffffu, mx, 0);

    float s = 0.f;
    #pragma unroll
    for (int u = 0; u < 16; u++) {
        v[u] = __expf(v[u] - mx);
        s += v[u];
    }
    s = warp_sum(s);
    __syncthreads();
    if (lane == 0) red[wid] = s;
    __syncthreads();
    s = warp_sum((lane < 8) ? red[lane] : 0.f);
    s = __shfl_sync(0xffffffffu, s, 0);

    float r = 1.f / s;
    #pragma unroll
    for (int u = 0; u < 16; u++)
        base[u * 256 + t] = v[u] * r;
}

// ---------------- zero ctx -------------------------------------------------
__global__ __launch_bounds__(256) void zero_kernel(float* __restrict__ p, int n)
{
    int i = blockIdx.x * 256 + threadIdx.x;
    if (i < n) p[i] = 0.f;
}

// ---------------- context[b,m,i,j] = sum_n k[i,n] * v[j,n] -----------------
#define NSPLIT 4
__global__ __launch_bounds__(256) void context_kernel(
    const float* __restrict__ qkv, float* __restrict__ ctx)
{
    __shared__ float Ks[64][65];   // [nn][i]
    __shared__ float Vs[64][65];   // [nn][j]
    int bm = blockIdx.x;           // BATCH*HEADS
    int m = bm & (HEADS - 1);
    int b = bm >> 3;
    const float* kbase = qkv + (size_t)b * O3 * NPOS + (size_t)(HID     + m * DH) * NPOS;
    const float* vbase = qkv + (size_t)b * O3 * NPOS + (size_t)(2 * HID + m * DH) * NPOS;
    int tid = threadIdx.x;
    int ti = tid & 15, tj = tid >> 4;

    float acc[4][4];
    #pragma unroll
    for (int a = 0; a < 4; a++)
        #pragma unroll
        for (int c = 0; c < 4; c++) acc[a][c] = 0.f;

    int nsplit = NPOS / NSPLIT;                    // 1024
    int nstart = blockIdx.y * nsplit;
    for (int nc = 0; nc < nsplit; nc += 64) {
        int nb = nstart + nc;
        #pragma unroll
        for (int l = 0; l < 16; l++) {
            int idx = l * 256 + tid;
            int i  = idx >> 6;
            int nn = idx & 63;
            Ks[nn][i] = kbase[(size_t)i * NPOS + nb + nn];
            Vs[nn][i] = vbase[(size_t)i * NPOS + nb + nn];
        }
        __syncthreads();
        #pragma unroll 8
        for (int nn = 0; nn < 64; nn++) {
            float ka[4], vb[4];
            #pragma unroll
            for (int a = 0; a < 4; a++) ka[a] = Ks[nn][ti * 4 + a];
            #pragma unroll
            for (int c = 0; c < 4; c++) vb[c] = Vs[nn][tj * 4 + c];
            #pragma unroll
            for (int a = 0; a < 4; a++)
                #pragma unroll
                for (int c = 0; c < 4; c++)
                    acc[a][c] += ka[a] * vb[c];
        }
        __syncthreads();
    }
    #pragma unroll
    for (int a = 0; a < 4; a++)
        #pragma unroll
        for (int c = 0; c < 4; c++)
            atomicAdd(&ctx[(size_t)bm * DH * DH + (ti * 4 + a) * DH + (tj * 4 + c)],
                      acc[a][c]);
}

// ---------------- attn_out[b, m*64+j, n] = sum_i ctx[i,j] * q[i,n] ---------
__global__ __launch_bounds__(128) void attnout_kernel(
    const float* __restrict__ qkv, const float* __restrict__ ctx,
    float* __restrict__ attn)
{
    __shared__ float cs[DH][DH];   // ctx[i][j]
    int bm = blockIdx.y;
    int m = bm & (HEADS - 1);
    int b = bm >> 3;
    const float* qbase = qkv + (size_t)b * O3 * NPOS + (size_t)(m * DH) * NPOS;
    int tid = threadIdx.x;

    #pragma unroll
    for (int l = 0; l < 32; l++)
        ((float*)cs)[l * 128 + tid] = ctx[(size_t)bm * DH * DH + l * 128 + tid];
    __syncthreads();

    int n = blockIdx.x * 128 + tid;
    float accj[DH];
    #pragma unroll
    for (int j = 0; j < DH; j++) accj[j] = 0.f;

    #pragma unroll 2
    for (int i = 0; i < DH; i++) {
        float qv = qbase[(size_t)i * NPOS + n];
        const float4* rowp = (const float4*)cs[i];
        #pragma unroll
        for (int j4 = 0; j4 < 16; j4++) {
            float4 c4 = rowp[j4];
            accj[j4 * 4 + 0] += c4.x * qv;
            accj[j4 * 4 + 1] += c4.y * qv;
            accj[j4 * 4 + 2] += c4.z * qv;
            accj[j4 * 4 + 3] += c4.w * qv;
        }
    }
    float* obase = attn + (size_t)b * CDIM * NPOS + (size_t)(m * DH) * NPOS + n;
    #pragma unroll
    for (int j = 0; j < DH; j++)
        obase[(size_t)j * NPOS] = accj[j];
}

// ---------------- launch ---------------------------------------------------
extern "C" void kernel_launch(void* const* d_in, const int* in_sizes, int n_in,
                              void* d_out, int out_size)
{
    const float* x          = (const float*)d_in[0];
    const float* norm_g     = (const float*)d_in[1];
    const float* qkv_w      = (const float*)d_in[2];
    const float* out_w      = (const float*)d_in[3];
    const float* out_b      = (const float*)d_in[4];
    const float* out_norm_g = (const float*)d_in[5];
    float* out = (float*)d_out;

    float *xn, *qkv, *attn, *ctx;
    cudaGetSymbolAddress((void**)&xn,   g_xn);
    cudaGetSymbolAddress((void**)&qkv,  g_qkv);
    cudaGetSymbolAddress((void**)&attn, g_attn);
    cudaGetSymbolAddress((void**)&ctx,  g_ctx);

    // 1. channel layernorm: x -> xn
    chan_ln_kernel<<<BATCH * NPOS / 256, 256>>>(x, norm_g, xn);

    // 2. qkv = qkv_w (1536x512) @ xn (b,512,4096)
    sgemm_kernel<<<dim3(NPOS / BN, O3 / BM, BATCH), 256>>>(
        qkv_w, xn, qkv, O3, NPOS, CDIM, nullptr);

    // 3. q: softmax over head-dim, * scale   4. k: softmax over n
    softmax_q_kernel<<<BATCH * HEADS * NPOS / 256, 256>>>(qkv);
    softmax_k_kernel<<<BATCH * HEADS * DH, 256>>>(qkv);

    // 5-6. context = k @ v^T (split-n + atomicAdd)
    int ctx_n = BATCH * HEADS * DH * DH;
    zero_kernel<<<(ctx_n + 255) / 256, 256>>>(ctx, ctx_n);
    context_kernel<<<dim3(BATCH * HEADS, NSPLIT), 256>>>(qkv, ctx);

    // 7. attn_out = ctx^T @ q
    attnout_kernel<<<dim3(NPOS / 128, BATCH * HEADS), 128>>>(qkv, ctx, attn);

    // 8. out proj: out_w (512x512) @ attn + out_b  -> d_out
    sgemm_kernel<<<dim3(NPOS / BN, HID / BM, BATCH), 256>>>(
        out_w, attn, out, HID, NPOS, CDIM, out_b);

    // 9. final channel layernorm in-place on d_out
    chan_ln_kernel<<<BATCH * NPOS / 256, 256>>>(out, out_norm_g, out);
}

// round 3
// speedup vs baseline: 2.1919x; 2.1919x over previous
#include <cuda_runtime.h>
#include <cuda_bf16.h>
#include <math_constants.h>
#include <cstdint>

#define BATCH 16
#define CDIM  512
#define NPOS  4096      // 64*64
#define O3    1536      // 3*HID
#define HID   512
#define HEADS 8
#define DH    64
#define EPSV  1e-5f
#define QSCALE 0.125f   // DH^-0.5

typedef __nv_bfloat16 bf16;

// ---------------- scratch (device globals; no allocations allowed) ---------
__device__ float g_mean [BATCH * NPOS];
__device__ float g_rstd [BATCH * NPOS];
__device__ bf16  g_xt_h [(size_t)BATCH * NPOS * CDIM];   // x normalized, channel-last, hi
__device__ bf16  g_xt_l [(size_t)BATCH * NPOS * CDIM];   // lo
__device__ float g_qkv  [(size_t)BATCH * O3   * NPOS];   // channel-major
__device__ float g_ctx  [BATCH * HEADS * DH * DH];
__device__ bf16  g_at_h [(size_t)BATCH * NPOS * HID];    // attn out, channel-last, hi
__device__ bf16  g_at_l [(size_t)BATCH * NPOS * HID];
__device__ float g_outpre[(size_t)BATCH * CDIM * NPOS];  // pre-final-LN, channel-major
__device__ bf16  g_wq_h [O3  * CDIM];
__device__ bf16  g_wq_l [O3  * CDIM];
__device__ bf16  g_wo_h [HID * CDIM];
__device__ bf16  g_wo_l [HID * CDIM];

// ======================= mma.sync helpers (sm_80+ features) ================
__device__ __forceinline__ uint32_t smem_to_u32(const void* p) {
    uint32_t a;
    asm("{ .reg .u64 t; cvta.to.shared.u64 t, %1; cvt.u32.u64 %0, t; }"
        : "=r"(a) : "l"(p));
    return a;
}
__device__ __forceinline__ void ldsm_x4(uint32_t& r0, uint32_t& r1,
                                        uint32_t& r2, uint32_t& r3, uint32_t addr) {
    asm volatile("ldmatrix.sync.aligned.m8n8.x4.shared.b16 {%0,%1,%2,%3}, [%4];"
        : "=r"(r0), "=r"(r1), "=r"(r2), "=r"(r3) : "r"(addr));
}
__device__ __forceinline__ void mma16816(float* d, const uint32_t* a,
                                         uint32_t b0, uint32_t b1) {
    asm volatile(
        "mma.sync.aligned.m16n8k16.row.col.f32.bf16.bf16.f32 "
        "{%0,%1,%2,%3},{%4,%5,%6,%7},{%8,%9},{%0,%1,%2,%3};"
        : "+f"(d[0]), "+f"(d[1]), "+f"(d[2]), "+f"(d[3])
        : "r"(a[0]), "r"(a[1]), "r"(a[2]), "r"(a[3]), "r"(b0), "r"(b1));
}

// ======================= split-bf16 tensor-core GEMM =======================
// C[b, bm+r, bn+c] = sum_k A[bm+r, k] * B[b, bn+c, k]  (+ bias[bm+r])
// A: [M_total, 512] bf16 hi/lo K-contiguous. B: [b, 4096, 512] bf16 hi/lo.
#define KC  64
#define LDT 72          // KC + 8 pad (bf16 units); row stride 144 B
#define TILE_B16 (128 * LDT)            // 9216 bf16 = 18432 B per operand tile
#define GEMM_SMEM (4 * TILE_B16 * 2)    // 73728 B

__global__ __launch_bounds__(256, 2) void gemm_mma(
    const bf16* __restrict__ Ah, const bf16* __restrict__ Al,
    const bf16* __restrict__ Bh, const bf16* __restrict__ Bl,
    float* __restrict__ C, const float* __restrict__ bias, int M_total)
{
    extern __shared__ bf16 sm[];
    bf16* sAh = sm;
    bf16* sAl = sm + TILE_B16;
    bf16* sBh = sm + 2 * TILE_B16;
    bf16* sBl = sm + 3 * TILE_B16;
    uint32_t uAh = smem_to_u32(sAh), uAl = smem_to_u32(sAl);
    uint32_t uBh = smem_to_u32(sBh), uBl = smem_to_u32(sBl);

    int tid = threadIdx.x, wid = tid >> 5, lane = tid & 31;
    int b = blockIdx.z, bm = blockIdx.y * 128, bn = blockIdx.x * 128;
    int warp_m = (wid & 3) * 32;        // 4 warps along M
    int warp_n = (wid >> 2) * 64;       // 2 warps along N

    // global pointers in uint4 units (8 bf16); row pitch = 512/8 = 64
    const uint4* gAh = (const uint4*)Ah + (size_t)bm * 64;
    const uint4* gAl = (const uint4*)Al + (size_t)bm * 64;
    const uint4* gBh = (const uint4*)Bh + ((size_t)b * NPOS + bn) * 64;
    const uint4* gBl = (const uint4*)Bl + ((size_t)b * NPOS + bn) * 64;

    float acc[2][8][4];
    #pragma unroll
    for (int mt = 0; mt < 2; mt++)
        #pragma unroll
        for (int nt = 0; nt < 8; nt++)
            #pragma unroll
            for (int f = 0; f < 4; f++) acc[mt][nt][f] = 0.f;

    // per-thread load coords: 1024 uint4 per operand tile, 4 per thread
    for (int kc = 0; kc < 8; kc++) {
        #pragma unroll
        for (int l = 0; l < 4; l++) {
            int i = l * 256 + tid;
            int row = i >> 3, c8 = i & 7;
            size_t go = (size_t)row * 64 + kc * 8 + c8;
            int so = row * LDT + c8 * 8;
            *(uint4*)&sAh[so] = gAh[go];
            *(uint4*)&sAl[so] = gAl[go];
            *(uint4*)&sBh[so] = gBh[go];
            *(uint4*)&sBl[so] = gBl[go];
        }
        __syncthreads();

        #pragma unroll
        for (int kk = 0; kk < 4; kk++) {
            // a-fragments: 2 m-tiles, hi and lo
            uint32_t ah[2][4], al[2][4];
            #pragma unroll
            for (int mt = 0; mt < 2; mt++) {
                uint32_t off = 2 * (uint32_t)((warp_m + mt * 16 + (lane & 15)) * LDT
                                              + kk * 16 + (lane >> 4) * 8);
                ldsm_x4(ah[mt][0], ah[mt][1], ah[mt][2], ah[mt][3], uAh + off);
                ldsm_x4(al[mt][0], al[mt][1], al[mt][2], al[mt][3], uAl + off);
            }
            #pragma unroll
            for (int nt2 = 0; nt2 < 4; nt2++) {
                uint32_t off = 2 * (uint32_t)((warp_n + nt2 * 16 + (lane & 15)) * LDT
                                              + kk * 16 + (lane >> 4) * 8);
                uint32_t bh0, bh1, bh2, bh3, bl0, bl1, bl2, bl3;
                ldsm_x4(bh0, bh1, bh2, bh3, uBh + off);
                ldsm_x4(bl0, bl1, bl2, bl3, uBl + off);
                #pragma unroll
                for (int mt = 0; mt < 2; mt++) {
                    // n-tile nt2*2 : frag {r0, r2};  nt2*2+1 : frag {r1, r3}
                    mma16816(acc[mt][nt2 * 2 + 0], ah[mt], bh0, bh2);
                    mma16816(acc[mt][nt2 * 2 + 1], ah[mt], bh1, bh3);
                    mma16816(acc[mt][nt2 * 2 + 0], ah[mt], bl0, bl2);
                    mma16816(acc[mt][nt2 * 2 + 1], ah[mt], bl1, bl3);
                    mma16816(acc[mt][nt2 * 2 + 0], al[mt], bh0, bh2);
                    mma16816(acc[mt][nt2 * 2 + 1], al[mt], bh1, bh3);
                }
            }
        }
        __syncthreads();
    }

    // writeout: c-frag rows r, r+8; cols 2*(lane%4), +1  -> float2 stores
    #pragma unroll
    for (int mt = 0; mt < 2; mt++) {
        int r0 = bm + warp_m + mt * 16 + (lane >> 2);
        float bb0 = bias ? bias[r0] : 0.f;
        float bb8 = bias ? bias[r0 + 8] : 0.f;
        #pragma unroll
        for (int nt = 0; nt < 8; nt++) {
            int col = bn + warp_n + nt * 8 + 2 * (lane & 3);
            float2 v0 = make_float2(acc[mt][nt][0] + bb0, acc[mt][nt][1] + bb0);
            float2 v1 = make_float2(acc[mt][nt][2] + bb8, acc[mt][nt][3] + bb8);
            *(float2*)&C[((size_t)b * M_total + r0    ) * NPOS + col] = v0;
            *(float2*)&C[((size_t)b * M_total + r0 + 8) * NPOS + col] = v1;
        }
    }
}

// ---------------- LN stats: mean/rstd over C per (b,p) ---------------------
__global__ __launch_bounds__(256) void ln_stats_kernel(
    const float* __restrict__ in, float* __restrict__ mean, float* __restrict__ rstd)
{
    int gid = blockIdx.x * 256 + threadIdx.x;
    int b = gid >> 12, p = gid & (NPOS - 1);
    const float* ip = in + (size_t)b * CDIM * NPOS + p;
    float s = 0.f, s2 = 0.f;
    #pragma unroll 8
    for (int c = 0; c < CDIM; c++) {
        float v = ip[(size_t)c * NPOS];
        s += v; s2 += v * v;
    }
    float m = s * (1.f / CDIM);
    float var = s2 * (1.f / CDIM) - m * m;
    mean[gid] = m;
    rstd[gid] = rsqrtf(var + EPSV);
}

// ---------------- normalize + transpose to channel-last, split bf16 --------
__global__ __launch_bounds__(256) void norm_transpose_kernel(
    const float* __restrict__ x, const float* __restrict__ g,
    const float* __restrict__ mean, const float* __restrict__ rstd,
    bf16* __restrict__ xh, bf16* __restrict__ xl)
{
    __shared__ float t[64][65];
    int b = blockIdx.z, c0 = blockIdx.y * 64, p0 = blockIdx.x * 64;
    int tid = threadIdx.x;
    #pragma unroll
    for (int l = 0; l < 16; l++) {
        int i = l * 256 + tid;
        int c = i >> 6, p = i & 63;
        float v = x[((size_t)b * CDIM + c0 + c) * NPOS + p0 + p];
        int sp = b * NPOS + p0 + p;
        t[p][c] = (v - mean[sp]) * rstd[sp] * g[c0 + c];
    }
    __syncthreads();
    #pragma unroll
    for (int l = 0; l < 16; l++) {
        int i = l * 256 + tid;
        int p = i >> 6, c = i & 63;
        float v = t[p][c];
        bf16 h = __float2bfloat16(v);
        bf16 lo = __float2bfloat16(v - __bfloat162float(h));
        size_t o = ((size_t)b * NPOS + p0 + p) * CDIM + c0 + c;
        xh[o] = h; xl[o] = lo;
    }
}

// ---------------- fp32 -> bf16 hi/lo split (weights) -----------------------
__global__ __launch_bounds__(256) void split_bf16_kernel(
    const float* __restrict__ w, bf16* __restrict__ h, bf16* __restrict__ l, int n)
{
    int i = blockIdx.x * 256 + threadIdx.x;
    if (i < n) {
        float v = w[i];
        bf16 hi = __float2bfloat16(v);
        h[i] = hi;
        l[i] = __float2bfloat16(v - __bfloat162float(hi));
    }
}

// ---------------- softmax over head-dim (axis=-2) for q, then *scale ------
__global__ __launch_bounds__(256) void softmax_q_kernel(float* __restrict__ qkv)
{
    int gid = blockIdx.x * 256 + threadIdx.x;
    int p = gid & (NPOS - 1);
    int bm = gid >> 12;
    int m = bm & (HEADS - 1);
    int b = bm >> 3;
    float* base = qkv + (size_t)b * O3 * NPOS + (size_t)(m * DH) * NPOS + p;

    float v[DH];
    float mx = -CUDART_INF_F;
    #pragma unroll
    for (int i = 0; i < DH; i++) {
        v[i] = base[(size_t)i * NPOS];
        mx = fmaxf(mx, v[i]);
    }
    float s = 0.f;
    #pragma unroll
    for (int i = 0; i < DH; i++) { v[i] = __expf(v[i] - mx); s += v[i]; }
    float r = QSCALE / s;
    #pragma unroll
    for (int i = 0; i < DH; i++) base[(size_t)i * NPOS] = v[i] * r;
}

// ---------------- softmax over n (axis=-1) for k ---------------------------
__device__ __forceinline__ float warp_max(float v) {
    #pragma unroll
    for (int o = 16; o > 0; o >>= 1) v = fmaxf(v, __shfl_xor_sync(0xffffffffu, v, o));
    return v;
}
__device__ __forceinline__ float warp_sum(float v) {
    #pragma unroll
    for (int o = 16; o > 0; o >>= 1) v += __shfl_xor_sync(0xffffffffu, v, o);
    return v;
}

__global__ __launch_bounds__(256) void softmax_k_kernel(float* __restrict__ qkv)
{
    __shared__ float red[8];
    int row = blockIdx.x;
    int i = row & (DH - 1);
    int m = (row >> 6) & (HEADS - 1);
    int b = row >> 9;
    float* base = qkv + (size_t)b * O3 * NPOS + (size_t)(HID + m * DH + i) * NPOS;
    int t = threadIdx.x;
    int lane = t & 31, wid = t >> 5;

    float v[16];
    float mx = -CUDART_INF_F;
    #pragma unroll
    for (int u = 0; u < 16; u++) {
        v[u] = base[u * 256 + t];
        mx = fmaxf(mx, v[u]);
    }
    mx = warp_max(mx);
    if (lane == 0) red[wid] = mx;
    __syncthreads();
    mx = warp_max((lane < 8) ? red[lane] : -CUDART_INF_F);
    mx = __shfl_sync(0xffffffffu, mx, 0);

    float s = 0.f;
    #pragma unroll
    for (int u = 0; u < 16; u++) { v[u] = __expf(v[u] - mx); s += v[u]; }
    s = warp_sum(s);
    __syncthreads();
    if (lane == 0) red[wid] = s;
    __syncthreads();
    s = warp_sum((lane < 8) ? red[lane] : 0.f);
    s = __shfl_sync(0xffffffffu, s, 0);

    float r = 1.f / s;
    #pragma unroll
    for (int u = 0; u < 16; u++) base[u * 256 + t] = v[u] * r;
}

// ---------------- zero ------------------------------------------------------
__global__ __launch_bounds__(256) void zero_kernel(float* __restrict__ p, int n)
{
    int i = blockIdx.x * 256 + threadIdx.x;
    if (i < n) p[i] = 0.f;
}

// ---------------- context[b,m,i,j] = sum_n k[i,n] * v[j,n] -----------------
#define NSPLIT 4
__global__ __launch_bounds__(256) void context_kernel(
    const float* __restrict__ qkv, float* __restrict__ ctx)
{
    __shared__ float Ks[64][65];
    __shared__ float Vs[64][65];
    int bm = blockIdx.x;
    int m = bm & (HEADS - 1);
    int b = bm >> 3;
    const float* kbase = qkv + (size_t)b * O3 * NPOS + (size_t)(HID     + m * DH) * NPOS;
    const float* vbase = qkv + (size_t)b * O3 * NPOS + (size_t)(2 * HID + m * DH) * NPOS;
    int tid = threadIdx.x;
    int ti = tid & 15, tj = tid >> 4;

    float acc[4][4];
    #pragma unroll
    for (int a = 0; a < 4; a++)
        #pragma unroll
        for (int c = 0; c < 4; c++) acc[a][c] = 0.f;

    int nsplit = NPOS / NSPLIT;
    int nstart = blockIdx.y * nsplit;
    for (int nc = 0; nc < nsplit; nc += 64) {
        int nb = nstart + nc;
        #pragma unroll
        for (int l = 0; l < 16; l++) {
            int idx = l * 256 + tid;
            int i = idx >> 6, nn = idx & 63;
            Ks[nn][i] = kbase[(size_t)i * NPOS + nb + nn];
            Vs[nn][i] = vbase[(size_t)i * NPOS + nb + nn];
        }
        __syncthreads();
        #pragma unroll 8
        for (int nn = 0; nn < 64; nn++) {
            float ka[4], vb[4];
            #pragma unroll
            for (int a = 0; a < 4; a++) ka[a] = Ks[nn][ti * 4 + a];
            #pragma unroll
            for (int c = 0; c < 4; c++) vb[c] = Vs[nn][tj * 4 + c];
            #pragma unroll
            for (int a = 0; a < 4; a++)
                #pragma unroll
                for (int c = 0; c < 4; c++) acc[a][c] += ka[a] * vb[c];
        }
        __syncthreads();
    }
    #pragma unroll
    for (int a = 0; a < 4; a++)
        #pragma unroll
        for (int c = 0; c < 4; c++)
            atomicAdd(&ctx[(size_t)bm * DH * DH + (ti * 4 + a) * DH + (tj * 4 + c)],
                      acc[a][c]);
}

// -------- attn_out -> channel-last bf16 hi/lo (for GEMM2 B operand) --------
// attn_t[b, n, m*64+j] = sum_i ctx[b,m,i,j] * q[b,m,i,n]
__global__ __launch_bounds__(128) void attnout_kernel(
    const float* __restrict__ qkv, const float* __restrict__ ctx,
    bf16* __restrict__ ath, bf16* __restrict__ atl)
{
    __shared__ float cs[DH][DH];        // 16 KB
    __shared__ float stage[128][64];    // 32 KB (rotated to dodge bank conflicts)
    int bm = blockIdx.y;
    int m = bm & (HEADS - 1);
    int b = bm >> 3;
    const float* qbase = qkv + (size_t)b * O3 * NPOS + (size_t)(m * DH) * NPOS;
    int tid = threadIdx.x;

    #pragma unroll
    for (int l = 0; l < 32; l++)
        ((float*)cs)[l * 128 + tid] = ctx[(size_t)bm * DH * DH + l * 128 + tid];
    __syncthreads();

    int n0 = blockIdx.x * 128;
    int n = n0 + tid;
    float accj[DH];
    #pragma unroll
    for (int j = 0; j < DH; j++) accj[j] = 0.f;

    #pragma unroll 2
    for (int i = 0; i < DH; i++) {
        float qv = qbase[(size_t)i * NPOS + n];
        const float4* rowp = (const float4*)cs[i];
        #pragma unroll
        for (int j4 = 0; j4 < 16; j4++) {
            float4 c4 = rowp[j4];
            accj[j4 * 4 + 0] += c4.x * qv;
            accj[j4 * 4 + 1] += c4.y * qv;
            accj[j4 * 4 + 2] += c4.z * qv;
            accj[j4 * 4 + 3] += c4.w * qv;
        }
    }
    // rotated store: stage[tid][(j+tid)&63]
    #pragma unroll
    for (int j = 0; j < DH; j++) stage[tid][(j + tid) & 63] = accj[j];
    __syncthreads();

    // coalesced channel-last write with hi/lo split
    #pragma unroll
    for (int l = 0; l < 64; l++) {
        int idx = l * 128 + tid;
        int p = idx >> 6, j = idx & 63;
        float v = stage[p][(j + p) & 63];
        bf16 h = __float2bfloat16(v);
        bf16 lo = __float2bfloat16(v - __bfloat162float(h));
        size_t o = ((size_t)b * NPOS + n0 + p) * HID + m * DH + j;
        ath[o] = h; atl[o] = lo;
    }
}

// ---------------- final channel layernorm (channel-major, 2-pass) ----------
__global__ __launch_bounds__(256) void chan_ln_kernel(
    const float* __restrict__ in, const float* __restrict__ g,
    float* __restrict__ out)
{
    int gid = blockIdx.x * 256 + threadIdx.x;
    int b = gid >> 12;
    int p = gid & (NPOS - 1);
    const float* ip = in  + (size_t)b * CDIM * NPOS + p;
    float*       op = out + (size_t)b * CDIM * NPOS + p;

    float s = 0.f, s2 = 0.f;
    #pragma unroll 8
    for (int c = 0; c < CDIM; c++) {
        float v = ip[(size_t)c * NPOS];
        s += v; s2 += v * v;
    }
    float mean = s * (1.f / CDIM);
    float var = s2 * (1.f / CDIM) - mean * mean;
    float rstd = rsqrtf(var + EPSV);

    #pragma unroll 8
    for (int c = 0; c < CDIM; c++) {
        float v = ip[(size_t)c * NPOS];
        op[(size_t)c * NPOS] = (v - mean) * rstd * g[c];
    }
}

// ---------------- launch ---------------------------------------------------
extern "C" void kernel_launch(void* const* d_in, const int* in_sizes, int n_in,
                              void* d_out, int out_size)
{
    const float* x          = (const float*)d_in[0];
    const float* norm_g     = (const float*)d_in[1];
    const float* qkv_w      = (const float*)d_in[2];
    const float* out_w      = (const float*)d_in[3];
    const float* out_b      = (const float*)d_in[4];
    const float* out_norm_g = (const float*)d_in[5];
    float* out = (float*)d_out;

    float *mean, *rstd, *qkv, *ctx, *outpre;
    bf16 *xth, *xtl, *ath, *atl, *wqh, *wql, *woh, *wol;
    cudaGetSymbolAddress((void**)&mean,   g_mean);
    cudaGetSymbolAddress((void**)&rstd,   g_rstd);
    cudaGetSymbolAddress((void**)&xth,    g_xt_h);
    cudaGetSymbolAddress((void**)&xtl,    g_xt_l);
    cudaGetSymbolAddress((void**)&qkv,    g_qkv);
    cudaGetSymbolAddress((void**)&ctx,    g_ctx);
    cudaGetSymbolAddress((void**)&ath,    g_at_h);
    cudaGetSymbolAddress((void**)&atl,    g_at_l);
    cudaGetSymbolAddress((void**)&outpre, g_outpre);
    cudaGetSymbolAddress((void**)&wqh,    g_wq_h);
    cudaGetSymbolAddress((void**)&wql,    g_wq_l);
    cudaGetSymbolAddress((void**)&woh,    g_wo_h);
    cudaGetSymbolAddress((void**)&wol,    g_wo_l);

    cudaFuncSetAttribute(gemm_mma, cudaFuncAttributeMaxDynamicSharedMemorySize,
                         GEMM_SMEM);

    // 1. LN stats + normalize-transpose-split (x -> xt hi/lo, channel-last)
    ln_stats_kernel<<<BATCH * NPOS / 256, 256>>>(x, mean, rstd);
    norm_transpose_kernel<<<dim3(NPOS / 64, CDIM / 64, BATCH), 256>>>(
        x, norm_g, mean, rstd, xth, xtl);

    // 2. weight splits
    split_bf16_kernel<<<(O3 * CDIM) / 256, 256>>>(qkv_w, wqh, wql, O3 * CDIM);
    split_bf16_kernel<<<(HID * CDIM) / 256, 256>>>(out_w, woh, wol, HID * CDIM);

    // 3. qkv GEMM (tensor cores): qkv[b,o,n] = sum_c W[o,c] * xt[b,n,c]
    gemm_mma<<<dim3(NPOS / 128, O3 / 128, BATCH), 256, GEMM_SMEM>>>(
        wqh, wql, xth, xtl, qkv, nullptr, O3);

    // 4. softmaxes
    softmax_q_kernel<<<BATCH * HEADS * NPOS / 256, 256>>>(qkv);
    softmax_k_kernel<<<BATCH * HEADS * DH, 256>>>(qkv);

    // 5. context = k @ v^T
    int ctx_n = BATCH * HEADS * DH * DH;
    zero_kernel<<<(ctx_n + 255) / 256, 256>>>(ctx, ctx_n);
    context_kernel<<<dim3(BATCH * HEADS, NSPLIT), 256>>>(qkv, ctx);

    // 6. attn out -> channel-last bf16 hi/lo
    attnout_kernel<<<dim3(NPOS / 128, BATCH * HEADS), 128>>>(qkv, ctx, ath, atl);

    // 7. out projection (tensor cores) + bias -> outpre (channel-major)
    gemm_mma<<<dim3(NPOS / 128, HID / 128, BATCH), 256, GEMM_SMEM>>>(
        woh, wol, ath, atl, outpre, out_b, HID);

    // 8. final channel LN -> d_out
    chan_ln_kernel<<<BATCH * NPOS / 256, 256>>>(outpre, out_norm_g, out);
}